// round 1
// baseline (speedup 1.0000x reference)
#include <cuda_runtime.h>
#include <math.h>

#define D 128
#define ES 20
#define FCUT 5.0f
#define EB 32      // edges per block (edge kernel)
#define NT 16      // nodes per block (node kernels)

// scratch: scalar_output (N x 384), N <= 24000
__device__ float g_so[24000 * 384];

__device__ __forceinline__ float silu_f(float x) {
    return x / (1.0f + __expf(-x));
}

// quad-aggregated vector reduction: lanes (t&3)==0 issue red.v4 covering 4 channels
__device__ __forceinline__ void red_quad(float* addr, float v) {
    float v1 = __shfl_down_sync(0xffffffffu, v, 1);
    float v2 = __shfl_down_sync(0xffffffffu, v, 2);
    float v3 = __shfl_down_sync(0xffffffffu, v, 3);
    if ((threadIdx.x & 3) == 0) {
        asm volatile("red.global.add.v4.f32 [%0], {%1,%2,%3,%4};"
                     :: "l"(addr), "f"(v), "f"(v1), "f"(v2), "f"(v3) : "memory");
    }
}

// ---------------------------------------------------------------------------
// Kernel A: scalar_output = silu(s @ Wm1 + bm1) @ Wm2 + bm2   -> g_so[n][384]
// block = 128 threads, 16 nodes; thread tile = (4 nodes) x (4 cols per group)
// ---------------------------------------------------------------------------
__global__ __launch_bounds__(128) void node_mlp_kernel(
    const float* __restrict__ s_in,
    const float* __restrict__ Wm1, const float* __restrict__ bm1,
    const float* __restrict__ Wm2, const float* __restrict__ bm2,
    int n)
{
    __shared__ float s_s[NT * D];
    __shared__ float h_s[NT * D];
    const int t  = threadIdx.x;
    const int n0 = blockIdx.x * NT;
    const int rg = t >> 5;          // row group: nodes rg*4 .. rg*4+3
    const int cq = (t & 31) * 4;    // column quad

    for (int i = t; i < NT * D; i += 128) {
        int nl = i >> 7;
        s_s[i] = (n0 + nl < n) ? s_in[(size_t)(n0 + nl) * D + (i & 127)] : 0.f;
    }
    __syncthreads();

    // phase 1: hidden (16 x 128)
    float acc[4][4];
    {
        float4 b = *(const float4*)&bm1[cq];
        #pragma unroll
        for (int i = 0; i < 4; i++) { acc[i][0]=b.x; acc[i][1]=b.y; acc[i][2]=b.z; acc[i][3]=b.w; }
    }
    #pragma unroll 4
    for (int k = 0; k < D; k++) {
        float4 w = *(const float4*)&Wm1[k * D + cq];
        #pragma unroll
        for (int i = 0; i < 4; i++) {
            float sv = s_s[(rg * 4 + i) * D + k];
            acc[i][0] += sv * w.x; acc[i][1] += sv * w.y;
            acc[i][2] += sv * w.z; acc[i][3] += sv * w.w;
        }
    }
    #pragma unroll
    for (int i = 0; i < 4; i++)
        #pragma unroll
        for (int j = 0; j < 4; j++)
            h_s[(rg * 4 + i) * D + cq + j] = silu_f(acc[i][j]);
    __syncthreads();

    // phase 2: out (16 x 384)
    float acc2[4][12];
    #pragma unroll
    for (int g = 0; g < 3; g++) {
        float4 b = *(const float4*)&bm2[g * D + cq];
        #pragma unroll
        for (int i = 0; i < 4; i++) {
            acc2[i][g*4+0]=b.x; acc2[i][g*4+1]=b.y; acc2[i][g*4+2]=b.z; acc2[i][g*4+3]=b.w;
        }
    }
    #pragma unroll 2
    for (int k = 0; k < D; k++) {
        float4 w0 = *(const float4*)&Wm2[k * 384 + cq];
        float4 w1 = *(const float4*)&Wm2[k * 384 + 128 + cq];
        float4 w2 = *(const float4*)&Wm2[k * 384 + 256 + cq];
        #pragma unroll
        for (int i = 0; i < 4; i++) {
            float hv = h_s[(rg * 4 + i) * D + k];
            acc2[i][0] += hv * w0.x; acc2[i][1]  += hv * w0.y;
            acc2[i][2] += hv * w0.z; acc2[i][3]  += hv * w0.w;
            acc2[i][4] += hv * w1.x; acc2[i][5]  += hv * w1.y;
            acc2[i][6] += hv * w1.z; acc2[i][7]  += hv * w1.w;
            acc2[i][8] += hv * w2.x; acc2[i][9]  += hv * w2.y;
            acc2[i][10]+= hv * w2.z; acc2[i][11] += hv * w2.w;
        }
    }
    #pragma unroll
    for (int i = 0; i < 4; i++) {
        int node = n0 + rg * 4 + i;
        if (node < n) {
            #pragma unroll
            for (int g = 0; g < 3; g++) {
                *(float4*)&g_so[(size_t)node * 384 + g * D + cq] =
                    make_float4(acc2[i][g*4+0], acc2[i][g*4+1], acc2[i][g*4+2], acc2[i][g*4+3]);
            }
        }
    }
}

// ---------------------------------------------------------------------------
// Kernel B: per-edge filter + messages + scatter-add into out_s / out_v
// block = 128 threads; thread t owns channels {t, t+128, t+256}; Wf in regs.
// ---------------------------------------------------------------------------
__global__ __launch_bounds__(128) void edge_kernel(
    const float* __restrict__ edge_states,
    const float* __restrict__ edge_vectors,
    const float* __restrict__ edge_norms,
    const int*   __restrict__ edge_index,
    const float* __restrict__ Wf, const float* __restrict__ bf,
    const float* __restrict__ v_in,
    float* __restrict__ out_s, float* __restrict__ out_v,
    int nE)
{
    __shared__ float es_T[ES * EB];
    __shared__ float fc_s[EB];
    __shared__ int   src_s[EB];
    __shared__ int   dst_s[EB];
    __shared__ float ev_s[3 * EB];

    const int t  = threadIdx.x;
    const int e0 = blockIdx.x * EB;

    // Wf columns for this thread's 3 channels -> registers (hot in L1/L2)
    float wf0[ES], wf1[ES], wf2[ES];
    #pragma unroll
    for (int k = 0; k < ES; k++) {
        wf0[k] = Wf[k * 384 + t];
        wf1[k] = Wf[k * 384 + 128 + t];
        wf2[k] = Wf[k * 384 + 256 + t];
    }
    const float bf0 = bf[t], bf1 = bf[128 + t], bf2 = bf[256 + t];

    // stage edge data (transposed edge_states for broadcast reads)
    for (int i = t; i < EB * ES; i += 128) {
        int el = i / ES, k = i % ES;
        es_T[k * EB + el] = (e0 + el < nE) ? edge_states[(size_t)(e0 + el) * ES + k] : 0.f;
    }
    for (int i = t; i < EB * 3; i += 128) {
        int el = i / 3, a = i % 3;
        ev_s[a * EB + el] = (e0 + el < nE) ? edge_vectors[(size_t)(e0 + el) * 3 + a] : 0.f;
    }
    if (t < EB) {
        int e = e0 + t;
        float fcv = 0.f;
        int s = 0, d = 0;
        if (e < nE) {
            float nr = edge_norms[e];
            if (nr < FCUT) fcv = 0.5f * (cospif(nr * (1.0f / FCUT)) + 1.0f);
            s = edge_index[2 * e];
            d = edge_index[2 * e + 1];
        }
        fc_s[t] = fcv; src_s[t] = s; dst_s[t] = d;
    }
    __syncthreads();

    for (int el = 0; el < EB; el++) {
        float fc = fc_s[el];
        if (fc == 0.f) continue;               // uniform across block
        int src = src_s[el], dst = dst_s[el];

        float fw0 = bf0, fw1 = bf1, fw2 = bf2;
        #pragma unroll
        for (int k = 0; k < ES; k++) {
            float esk = es_T[k * EB + el];
            fw0 += esk * wf0[k];
            fw1 += esk * wf1[k];
            fw2 += esk * wf2[k];
        }
        const float* sop = g_so + (size_t)src * 384;
        float gn = fw0 * fc * sop[t];
        float ge = fw1 * fc * sop[128 + t];
        float ms = fw2 * fc * sop[256 + t];

        const float* vp = v_in + (size_t)src * 384;
        float ev0 = ev_s[el], ev1 = ev_s[EB + el], ev2 = ev_s[2 * EB + el];
        float mv0 = vp[t]       * gn + ge * ev0;
        float mv1 = vp[128 + t] * gn + ge * ev1;
        float mv2 = vp[256 + t] * gn + ge * ev2;

        red_quad(out_s + (size_t)dst * D + t, ms);
        float* vb = out_v + (size_t)dst * 384;
        red_quad(vb + t,       mv0);
        red_quad(vb + 128 + t, mv1);
        red_quad(vb + 256 + t, mv2);
    }
}

// ---------------------------------------------------------------------------
// Kernel C: node update (Uv, Vv, Vv_sq, ip, a-MLP, final s/v) in-place on d_out
// block = 128 threads, 16 nodes. Dynamic smem ~104KB.
// ---------------------------------------------------------------------------
__global__ __launch_bounds__(128) void node_update_kernel(
    const float* __restrict__ WU, const float* __restrict__ WV,
    const float* __restrict__ Wa1, const float* __restrict__ ba1,
    const float* __restrict__ Wa2, const float* __restrict__ ba2,
    float* __restrict__ out_s, float* __restrict__ out_v,
    int n)
{
    extern __shared__ float sm[];
    float* s_s    = sm;                 // NT*128
    float* v_s    = s_s    + NT * 128;  // NT*384
    float* Uv_s   = v_s    + NT * 384;  // NT*384
    float* vvsq_s = Uv_s   + NT * 384;  // NT*128
    float* ip_s   = vvsq_s + NT * 128;  // NT*128
    float* h_s    = ip_s   + NT * 128;  // NT*128
    float* a_s    = h_s    + NT * 128;  // NT*384

    const int t  = threadIdx.x;
    const int n0 = blockIdx.x * NT;
    const int rg = t >> 5;
    const int cq = (t & 31) * 4;

    for (int i = t; i < NT * 128; i += 128) {
        int nl = i >> 7;
        s_s[i] = (n0 + nl < n) ? out_s[(size_t)(n0 + nl) * D + (i & 127)] : 0.f;
    }
    for (int i = t; i < NT * 384; i += 128) {
        int nl = i / 384;
        v_s[i] = (n0 + nl < n) ? out_v[(size_t)(n0 + nl) * 384 + (i % 384)] : 0.f;
    }
    __syncthreads();

    // U & V GEMMs: rows r = rg*12..rg*12+11 (r = node_local*3 + axis), cols cq..cq+3
    float accU[12][4], accV[12][4];
    #pragma unroll
    for (int r = 0; r < 12; r++)
        #pragma unroll
        for (int j = 0; j < 4; j++) { accU[r][j] = 0.f; accV[r][j] = 0.f; }

    #pragma unroll 2
    for (int k = 0; k < D; k++) {
        float4 wu = *(const float4*)&WU[k * D + cq];
        float4 wv = *(const float4*)&WV[k * D + cq];
        #pragma unroll
        for (int r = 0; r < 12; r++) {
            float vv = v_s[(rg * 12 + r) * D + k];
            accU[r][0] += vv * wu.x; accU[r][1] += vv * wu.y;
            accU[r][2] += vv * wu.z; accU[r][3] += vv * wu.w;
            accV[r][0] += vv * wv.x; accV[r][1] += vv * wv.y;
            accV[r][2] += vv * wv.z; accV[r][3] += vv * wv.w;
        }
    }

    // vvsq / ip per (node, col); store Uv for final update
    #pragma unroll
    for (int nl = 0; nl < 4; nl++) {
        float q[4] = {0.f, 0.f, 0.f, 0.f};
        float p[4] = {0.f, 0.f, 0.f, 0.f};
        #pragma unroll
        for (int a = 0; a < 3; a++) {
            int r = nl * 3 + a;
            #pragma unroll
            for (int j = 0; j < 4; j++) {
                q[j] += accV[r][j] * accV[r][j];
                p[j] += accU[r][j] * accV[r][j];
                Uv_s[(rg * 12 + r) * D + cq + j] = accU[r][j];
            }
        }
        #pragma unroll
        for (int j = 0; j < 4; j++) {
            vvsq_s[(rg * 4 + nl) * D + cq + j] = q[j];
            ip_s[(rg * 4 + nl) * D + cq + j]   = p[j];
        }
    }
    __syncthreads();

    // a-MLP hidden: concat([s, vvsq]) @ Wa1 + ba1 -> silu
    float hacc[4][4];
    {
        float4 b = *(const float4*)&ba1[cq];
        #pragma unroll
        for (int i = 0; i < 4; i++) { hacc[i][0]=b.x; hacc[i][1]=b.y; hacc[i][2]=b.z; hacc[i][3]=b.w; }
    }
    #pragma unroll 2
    for (int k = 0; k < D; k++) {
        float4 w = *(const float4*)&Wa1[k * D + cq];
        #pragma unroll
        for (int i = 0; i < 4; i++) {
            float sv = s_s[(rg * 4 + i) * D + k];
            hacc[i][0] += sv * w.x; hacc[i][1] += sv * w.y;
            hacc[i][2] += sv * w.z; hacc[i][3] += sv * w.w;
        }
    }
    #pragma unroll 2
    for (int k = 0; k < D; k++) {
        float4 w = *(const float4*)&Wa1[(D + k) * D + cq];
        #pragma unroll
        for (int i = 0; i < 4; i++) {
            float qv = vvsq_s[(rg * 4 + i) * D + k];
            hacc[i][0] += qv * w.x; hacc[i][1] += qv * w.y;
            hacc[i][2] += qv * w.z; hacc[i][3] += qv * w.w;
        }
    }
    #pragma unroll
    for (int i = 0; i < 4; i++)
        #pragma unroll
        for (int j = 0; j < 4; j++)
            h_s[(rg * 4 + i) * D + cq + j] = silu_f(hacc[i][j]);
    __syncthreads();

    // a = h @ Wa2 + ba2  (16 x 384)
    float aacc[4][12];
    #pragma unroll
    for (int g = 0; g < 3; g++) {
        float4 b = *(const float4*)&ba2[g * D + cq];
        #pragma unroll
        for (int i = 0; i < 4; i++) {
            aacc[i][g*4+0]=b.x; aacc[i][g*4+1]=b.y; aacc[i][g*4+2]=b.z; aacc[i][g*4+3]=b.w;
        }
    }
    #pragma unroll 2
    for (int k = 0; k < D; k++) {
        float4 w0 = *(const float4*)&Wa2[k * 384 + cq];
        float4 w1 = *(const float4*)&Wa2[k * 384 + 128 + cq];
        float4 w2 = *(const float4*)&Wa2[k * 384 + 256 + cq];
        #pragma unroll
        for (int i = 0; i < 4; i++) {
            float hv = h_s[(rg * 4 + i) * D + k];
            aacc[i][0] += hv * w0.x; aacc[i][1]  += hv * w0.y;
            aacc[i][2] += hv * w0.z; aacc[i][3]  += hv * w0.w;
            aacc[i][4] += hv * w1.x; aacc[i][5]  += hv * w1.y;
            aacc[i][6] += hv * w1.z; aacc[i][7]  += hv * w1.w;
            aacc[i][8] += hv * w2.x; aacc[i][9]  += hv * w2.y;
            aacc[i][10]+= hv * w2.z; aacc[i][11] += hv * w2.w;
        }
    }
    #pragma unroll
    for (int i = 0; i < 4; i++)
        #pragma unroll
        for (int g = 0; g < 3; g++)
            *(float4*)&a_s[(rg * 4 + i) * 384 + g * D + cq] =
                make_float4(aacc[i][g*4+0], aacc[i][g*4+1], aacc[i][g*4+2], aacc[i][g*4+3]);
    __syncthreads();

    // final update (channel t, all 16 nodes)
    for (int nl = 0; nl < NT; nl++) {
        int node = n0 + nl;
        if (node >= n) break;
        float a_ss = a_s[nl * 384 + t];
        float a_sv = a_s[nl * 384 + 128 + t];
        float a_vv = a_s[nl * 384 + 256 + t];
        out_s[(size_t)node * D + t] = s_s[nl * D + t] + a_ss + a_sv * ip_s[nl * D + t];
        #pragma unroll
        for (int a = 0; a < 3; a++) {
            size_t off = (size_t)node * 384 + a * D + t;
            out_v[off] = v_s[nl * 384 + a * D + t] + a_vv * Uv_s[nl * 384 + a * D + t];
        }
    }
}

// ---------------------------------------------------------------------------
extern "C" void kernel_launch(void* const* d_in, const int* in_sizes, int n_in,
                              void* d_out, int out_size)
{
    const float* s_in  = (const float*)d_in[0];
    const float* v_in  = (const float*)d_in[1];
    const float* e_st  = (const float*)d_in[2];
    const float* e_vec = (const float*)d_in[3];
    const float* e_nrm = (const float*)d_in[4];
    const int*   e_idx = (const int*)  d_in[5];
    const float* Wf  = (const float*)d_in[6];
    const float* bf  = (const float*)d_in[7];
    const float* Wm1 = (const float*)d_in[8];
    const float* bm1 = (const float*)d_in[9];
    const float* Wm2 = (const float*)d_in[10];
    const float* bm2 = (const float*)d_in[11];
    const float* WU  = (const float*)d_in[12];
    const float* WV  = (const float*)d_in[13];
    const float* Wa1 = (const float*)d_in[14];
    const float* ba1 = (const float*)d_in[15];
    const float* Wa2 = (const float*)d_in[16];
    const float* ba2 = (const float*)d_in[17];

    const int n  = in_sizes[0] / D;
    const int nE = in_sizes[2] / ES;

    float* out_s = (float*)d_out;
    float* out_v = out_s + (size_t)n * D;

    const size_t smem_c = (size_t)NT * (128 + 384 + 384 + 128 + 128 + 128 + 384) * sizeof(float);
    cudaFuncSetAttribute(node_update_kernel,
                         cudaFuncAttributeMaxDynamicSharedMemorySize, (int)smem_c);

    // init accumulators: s_sum = s0, v_sum = v0 (edge kernel adds messages)
    cudaMemcpyAsync(out_s, s_in, (size_t)n * D * sizeof(float),   cudaMemcpyDeviceToDevice, 0);
    cudaMemcpyAsync(out_v, v_in, (size_t)n * 384 * sizeof(float), cudaMemcpyDeviceToDevice, 0);

    node_mlp_kernel<<<(n + NT - 1) / NT, 128>>>(s_in, Wm1, bm1, Wm2, bm2, n);

    edge_kernel<<<(nE + EB - 1) / EB, 128>>>(e_st, e_vec, e_nrm, e_idx,
                                             Wf, bf, v_in, out_s, out_v, nE);

    node_update_kernel<<<(n + NT - 1) / NT, 128, smem_c>>>(WU, WV, Wa1, ba1, Wa2, ba2,
                                                           out_s, out_v, n);
}

// round 2
// speedup vs baseline: 1.3629x; 1.3629x over previous
#include <cuda_runtime.h>
#include <math.h>

#define D 128
#define ES 20
#define FCUT 5.0f
#define NT 16      // nodes per block (node kernels)
#define CH 8       // edges per staging chunk (aggregate kernel)
#define MAXN 20000
#define MAXE 600000

// ---- device scratch (static, no allocs) ----
__device__ float g_so[MAXN * 384];          // scalar_output
__device__ int   g_cnt[MAXN];               // per-dst degree
__device__ int   g_rowoff[MAXN + 1];        // CSR offsets
__device__ int   g_cursor[MAXN];            // scatter cursors
__device__ int   g_src[MAXE];               // CSR-ordered src
__device__ float g_fc[MAXE];                // CSR-ordered cutoff weight
__device__ float g_ev[MAXE * 3];            // CSR-ordered edge vectors
__device__ float g_es[MAXE * ES];           // CSR-ordered edge states

__device__ __forceinline__ float silu_f(float x) {
    return x / (1.0f + __expf(-x));
}

// ---------------------------------------------------------------------------
// CSR build
// ---------------------------------------------------------------------------
__global__ void zero_kernel(int n) {
    int i = blockIdx.x * blockDim.x + threadIdx.x;
    if (i < n) g_cnt[i] = 0;
}

__global__ void hist_kernel(const int* __restrict__ edge_index, int nE) {
    int e = blockIdx.x * blockDim.x + threadIdx.x;
    if (e < nE) atomicAdd(&g_cnt[edge_index[2 * e + 1]], 1);
}

__global__ void scan_kernel(int n) {
    __shared__ int sh[1024];
    __shared__ int carry_s;
    const int t = threadIdx.x;
    if (t == 0) { carry_s = 0; g_rowoff[0] = 0; }
    __syncthreads();
    for (int base = 0; base < n; base += 1024) {
        int v = (base + t < n) ? g_cnt[base + t] : 0;
        sh[t] = v;
        __syncthreads();
        for (int off = 1; off < 1024; off <<= 1) {
            int x = sh[t];
            int y = (t >= off) ? sh[t - off] : 0;
            __syncthreads();
            sh[t] = x + y;
            __syncthreads();
        }
        int incl = sh[t];
        int carry = carry_s;
        if (base + t < n) {
            g_rowoff[base + t + 1] = carry + incl;
            g_cursor[base + t]     = carry + incl - v;
        }
        __syncthreads();
        if (t == 1023) carry_s = carry + incl;
        __syncthreads();
    }
}

__global__ void scatter_kernel(
    const float* __restrict__ edge_states,
    const float* __restrict__ edge_vectors,
    const float* __restrict__ edge_norms,
    const int*   __restrict__ edge_index,
    int nE)
{
    int e = blockIdx.x * blockDim.x + threadIdx.x;
    if (e >= nE) return;
    int dst = edge_index[2 * e + 1];
    int pos = atomicAdd(&g_cursor[dst], 1);
    g_src[pos] = edge_index[2 * e];
    float nr = edge_norms[e];
    g_fc[pos] = (nr < FCUT) ? 0.5f * (cospif(nr * (1.0f / FCUT)) + 1.0f) : 0.f;
    g_ev[pos * 3 + 0] = edge_vectors[(size_t)e * 3 + 0];
    g_ev[pos * 3 + 1] = edge_vectors[(size_t)e * 3 + 1];
    g_ev[pos * 3 + 2] = edge_vectors[(size_t)e * 3 + 2];
    #pragma unroll
    for (int k = 0; k < ES; k++)
        g_es[(size_t)pos * ES + k] = edge_states[(size_t)e * ES + k];
}

// ---------------------------------------------------------------------------
// Kernel A: scalar_output = silu(s @ Wm1 + bm1) @ Wm2 + bm2   -> g_so[n][384]
// ---------------------------------------------------------------------------
__global__ __launch_bounds__(128) void node_mlp_kernel(
    const float* __restrict__ s_in,
    const float* __restrict__ Wm1, const float* __restrict__ bm1,
    const float* __restrict__ Wm2, const float* __restrict__ bm2,
    int n)
{
    __shared__ float s_s[NT * D];
    __shared__ float h_s[NT * D];
    const int t  = threadIdx.x;
    const int n0 = blockIdx.x * NT;
    const int rg = t >> 5;
    const int cq = (t & 31) * 4;

    for (int i = t; i < NT * D; i += 128) {
        int nl = i >> 7;
        s_s[i] = (n0 + nl < n) ? s_in[(size_t)(n0 + nl) * D + (i & 127)] : 0.f;
    }
    __syncthreads();

    float acc[4][4];
    {
        float4 b = *(const float4*)&bm1[cq];
        #pragma unroll
        for (int i = 0; i < 4; i++) { acc[i][0]=b.x; acc[i][1]=b.y; acc[i][2]=b.z; acc[i][3]=b.w; }
    }
    #pragma unroll 4
    for (int k = 0; k < D; k++) {
        float4 w = *(const float4*)&Wm1[k * D + cq];
        #pragma unroll
        for (int i = 0; i < 4; i++) {
            float sv = s_s[(rg * 4 + i) * D + k];
            acc[i][0] += sv * w.x; acc[i][1] += sv * w.y;
            acc[i][2] += sv * w.z; acc[i][3] += sv * w.w;
        }
    }
    #pragma unroll
    for (int i = 0; i < 4; i++)
        #pragma unroll
        for (int j = 0; j < 4; j++)
            h_s[(rg * 4 + i) * D + cq + j] = silu_f(acc[i][j]);
    __syncthreads();

    float acc2[4][12];
    #pragma unroll
    for (int g = 0; g < 3; g++) {
        float4 b = *(const float4*)&bm2[g * D + cq];
        #pragma unroll
        for (int i = 0; i < 4; i++) {
            acc2[i][g*4+0]=b.x; acc2[i][g*4+1]=b.y; acc2[i][g*4+2]=b.z; acc2[i][g*4+3]=b.w;
        }
    }
    #pragma unroll 2
    for (int k = 0; k < D; k++) {
        float4 w0 = *(const float4*)&Wm2[k * 384 + cq];
        float4 w1 = *(const float4*)&Wm2[k * 384 + 128 + cq];
        float4 w2 = *(const float4*)&Wm2[k * 384 + 256 + cq];
        #pragma unroll
        for (int i = 0; i < 4; i++) {
            float hv = h_s[(rg * 4 + i) * D + k];
            acc2[i][0] += hv * w0.x; acc2[i][1]  += hv * w0.y;
            acc2[i][2] += hv * w0.z; acc2[i][3]  += hv * w0.w;
            acc2[i][4] += hv * w1.x; acc2[i][5]  += hv * w1.y;
            acc2[i][6] += hv * w1.z; acc2[i][7]  += hv * w1.w;
            acc2[i][8] += hv * w2.x; acc2[i][9]  += hv * w2.y;
            acc2[i][10]+= hv * w2.z; acc2[i][11] += hv * w2.w;
        }
    }
    #pragma unroll
    for (int i = 0; i < 4; i++) {
        int node = n0 + rg * 4 + i;
        if (node < n) {
            #pragma unroll
            for (int g = 0; g < 3; g++)
                *(float4*)&g_so[(size_t)node * 384 + g * D + cq] =
                    make_float4(acc2[i][g*4+0], acc2[i][g*4+1], acc2[i][g*4+2], acc2[i][g*4+3]);
        }
    }
}

// ---------------------------------------------------------------------------
// Kernel B: node-centric aggregation. Block = 128 threads = 1 dst node.
// Thread t owns channels {t, t+128, t+256}. Wf columns live in registers.
// Accumulates s_in + sum(messages_scalar), v_in + sum(messages_vector)
// entirely in registers -> single store. Zero atomics.
// ---------------------------------------------------------------------------
__global__ __launch_bounds__(128) void aggregate_kernel(
    const float* __restrict__ s_in,
    const float* __restrict__ v_in,
    const float* __restrict__ Wf, const float* __restrict__ bf,
    float* __restrict__ out_s, float* __restrict__ out_v,
    int n)
{
    const int j = blockIdx.x;
    const int t = threadIdx.x;
    if (j >= n) return;

    float wf0[ES], wf1[ES], wf2[ES];
    #pragma unroll
    for (int k = 0; k < ES; k++) {
        wf0[k] = Wf[k * 384 + t];
        wf1[k] = Wf[k * 384 + 128 + t];
        wf2[k] = Wf[k * 384 + 256 + t];
    }
    const float bf0 = bf[t], bf1 = bf[128 + t], bf2 = bf[256 + t];

    float acc_s = s_in[(size_t)j * D + t];
    float av0   = v_in[(size_t)j * 384 + t];
    float av1   = v_in[(size_t)j * 384 + 128 + t];
    float av2   = v_in[(size_t)j * 384 + 256 + t];

    const int start = g_rowoff[j];
    const int end   = g_rowoff[j + 1];

    __shared__ float es_s[CH * ES];
    __shared__ float ev_s[CH * 3];
    __shared__ float fc_s[CH];
    __shared__ int   src_s[CH];

    for (int base = start; base < end; base += CH) {
        const int m = min(CH, end - base);
        __syncthreads();
        for (int i = t; i < m * ES; i += 128) es_s[i] = g_es[(size_t)base * ES + i];
        if (t < m * 3) ev_s[t] = g_ev[(size_t)base * 3 + t];
        if (t < m) { fc_s[t] = g_fc[base + t]; src_s[t] = g_src[base + t]; }
        __syncthreads();

        #pragma unroll
        for (int el = 0; el < CH; el++) {
            if (el >= m) break;
            const float fc = fc_s[el];
            const int  src = src_s[el];
            const float* sop = g_so + (size_t)src * 384;
            const float* vp  = v_in + (size_t)src * 384;
            // issue gathers early; filter GEMM hides their latency
            float so0 = sop[t], so1 = sop[128 + t], so2 = sop[256 + t];
            float vv0 = vp[t],  vv1 = vp[128 + t],  vv2 = vp[256 + t];

            float fw0 = bf0, fw1 = bf1, fw2 = bf2;
            #pragma unroll
            for (int k = 0; k < ES; k++) {
                const float esk = es_s[el * ES + k];
                fw0 += esk * wf0[k];
                fw1 += esk * wf1[k];
                fw2 += esk * wf2[k];
            }
            const float gn = fw0 * fc * so0;   // gate_nodes
            const float ge = fw1 * fc * so1;   // gate_edges
            acc_s += fw2 * fc * so2;           // messages_scalar

            const float e0 = ev_s[el * 3 + 0], e1 = ev_s[el * 3 + 1], e2 = ev_s[el * 3 + 2];
            av0 += vv0 * gn + ge * e0;
            av1 += vv1 * gn + ge * e1;
            av2 += vv2 * gn + ge * e2;
        }
    }

    out_s[(size_t)j * D + t]         = acc_s;
    out_v[(size_t)j * 384 + t]       = av0;
    out_v[(size_t)j * 384 + 128 + t] = av1;
    out_v[(size_t)j * 384 + 256 + t] = av2;
}

// ---------------------------------------------------------------------------
// Kernel C: node update (Uv, Vv, Vv_sq, ip, a-MLP, final s/v) in-place
// ---------------------------------------------------------------------------
__global__ __launch_bounds__(128) void node_update_kernel(
    const float* __restrict__ WU, const float* __restrict__ WV,
    const float* __restrict__ Wa1, const float* __restrict__ ba1,
    const float* __restrict__ Wa2, const float* __restrict__ ba2,
    float* __restrict__ out_s, float* __restrict__ out_v,
    int n)
{
    extern __shared__ float sm[];
    float* s_s    = sm;                 // NT*128
    float* v_s    = s_s    + NT * 128;  // NT*384
    float* Uv_s   = v_s    + NT * 384;  // NT*384
    float* vvsq_s = Uv_s   + NT * 384;  // NT*128
    float* ip_s   = vvsq_s + NT * 128;  // NT*128
    float* h_s    = ip_s   + NT * 128;  // NT*128
    float* a_s    = h_s    + NT * 128;  // NT*384

    const int t  = threadIdx.x;
    const int n0 = blockIdx.x * NT;
    const int rg = t >> 5;
    const int cq = (t & 31) * 4;

    for (int i = t; i < NT * 128; i += 128) {
        int nl = i >> 7;
        s_s[i] = (n0 + nl < n) ? out_s[(size_t)(n0 + nl) * D + (i & 127)] : 0.f;
    }
    for (int i = t; i < NT * 384; i += 128) {
        int nl = i / 384;
        v_s[i] = (n0 + nl < n) ? out_v[(size_t)(n0 + nl) * 384 + (i % 384)] : 0.f;
    }
    __syncthreads();

    float accU[12][4], accV[12][4];
    #pragma unroll
    for (int r = 0; r < 12; r++)
        #pragma unroll
        for (int j = 0; j < 4; j++) { accU[r][j] = 0.f; accV[r][j] = 0.f; }

    #pragma unroll 2
    for (int k = 0; k < D; k++) {
        float4 wu = *(const float4*)&WU[k * D + cq];
        float4 wv = *(const float4*)&WV[k * D + cq];
        #pragma unroll
        for (int r = 0; r < 12; r++) {
            float vv = v_s[(rg * 12 + r) * D + k];
            accU[r][0] += vv * wu.x; accU[r][1] += vv * wu.y;
            accU[r][2] += vv * wu.z; accU[r][3] += vv * wu.w;
            accV[r][0] += vv * wv.x; accV[r][1] += vv * wv.y;
            accV[r][2] += vv * wv.z; accV[r][3] += vv * wv.w;
        }
    }

    #pragma unroll
    for (int nl = 0; nl < 4; nl++) {
        float q[4] = {0.f, 0.f, 0.f, 0.f};
        float p[4] = {0.f, 0.f, 0.f, 0.f};
        #pragma unroll
        for (int a = 0; a < 3; a++) {
            int r = nl * 3 + a;
            #pragma unroll
            for (int j = 0; j < 4; j++) {
                q[j] += accV[r][j] * accV[r][j];
                p[j] += accU[r][j] * accV[r][j];
                Uv_s[(rg * 12 + r) * D + cq + j] = accU[r][j];
            }
        }
        #pragma unroll
        for (int j = 0; j < 4; j++) {
            vvsq_s[(rg * 4 + nl) * D + cq + j] = q[j];
            ip_s[(rg * 4 + nl) * D + cq + j]   = p[j];
        }
    }
    __syncthreads();

    float hacc[4][4];
    {
        float4 b = *(const float4*)&ba1[cq];
        #pragma unroll
        for (int i = 0; i < 4; i++) { hacc[i][0]=b.x; hacc[i][1]=b.y; hacc[i][2]=b.z; hacc[i][3]=b.w; }
    }
    #pragma unroll 2
    for (int k = 0; k < D; k++) {
        float4 w = *(const float4*)&Wa1[k * D + cq];
        #pragma unroll
        for (int i = 0; i < 4; i++) {
            float sv = s_s[(rg * 4 + i) * D + k];
            hacc[i][0] += sv * w.x; hacc[i][1] += sv * w.y;
            hacc[i][2] += sv * w.z; hacc[i][3] += sv * w.w;
        }
    }
    #pragma unroll 2
    for (int k = 0; k < D; k++) {
        float4 w = *(const float4*)&Wa1[(D + k) * D + cq];
        #pragma unroll
        for (int i = 0; i < 4; i++) {
            float qv = vvsq_s[(rg * 4 + i) * D + k];
            hacc[i][0] += qv * w.x; hacc[i][1] += qv * w.y;
            hacc[i][2] += qv * w.z; hacc[i][3] += qv * w.w;
        }
    }
    #pragma unroll
    for (int i = 0; i < 4; i++)
        #pragma unroll
        for (int j = 0; j < 4; j++)
            h_s[(rg * 4 + i) * D + cq + j] = silu_f(hacc[i][j]);
    __syncthreads();

    float aacc[4][12];
    #pragma unroll
    for (int g = 0; g < 3; g++) {
        float4 b = *(const float4*)&ba2[g * D + cq];
        #pragma unroll
        for (int i = 0; i < 4; i++) {
            aacc[i][g*4+0]=b.x; aacc[i][g*4+1]=b.y; aacc[i][g*4+2]=b.z; aacc[i][g*4+3]=b.w;
        }
    }
    #pragma unroll 2
    for (int k = 0; k < D; k++) {
        float4 w0 = *(const float4*)&Wa2[k * 384 + cq];
        float4 w1 = *(const float4*)&Wa2[k * 384 + 128 + cq];
        float4 w2 = *(const float4*)&Wa2[k * 384 + 256 + cq];
        #pragma unroll
        for (int i = 0; i < 4; i++) {
            float hv = h_s[(rg * 4 + i) * D + k];
            aacc[i][0] += hv * w0.x; aacc[i][1]  += hv * w0.y;
            aacc[i][2] += hv * w0.z; aacc[i][3]  += hv * w0.w;
            aacc[i][4] += hv * w1.x; aacc[i][5]  += hv * w1.y;
            aacc[i][6] += hv * w1.z; aacc[i][7]  += hv * w1.w;
            aacc[i][8] += hv * w2.x; aacc[i][9]  += hv * w2.y;
            aacc[i][10]+= hv * w2.z; aacc[i][11] += hv * w2.w;
        }
    }
    #pragma unroll
    for (int i = 0; i < 4; i++)
        #pragma unroll
        for (int g = 0; g < 3; g++)
            *(float4*)&a_s[(rg * 4 + i) * 384 + g * D + cq] =
                make_float4(aacc[i][g*4+0], aacc[i][g*4+1], aacc[i][g*4+2], aacc[i][g*4+3]);
    __syncthreads();

    for (int nl = 0; nl < NT; nl++) {
        int node = n0 + nl;
        if (node >= n) break;
        float a_ss = a_s[nl * 384 + t];
        float a_sv = a_s[nl * 384 + 128 + t];
        float a_vv = a_s[nl * 384 + 256 + t];
        out_s[(size_t)node * D + t] = s_s[nl * D + t] + a_ss + a_sv * ip_s[nl * D + t];
        #pragma unroll
        for (int a = 0; a < 3; a++) {
            size_t off = (size_t)node * 384 + a * D + t;
            out_v[off] = v_s[nl * 384 + a * D + t] + a_vv * Uv_s[nl * 384 + a * D + t];
        }
    }
}

// ---------------------------------------------------------------------------
extern "C" void kernel_launch(void* const* d_in, const int* in_sizes, int n_in,
                              void* d_out, int out_size)
{
    const float* s_in  = (const float*)d_in[0];
    const float* v_in  = (const float*)d_in[1];
    const float* e_st  = (const float*)d_in[2];
    const float* e_vec = (const float*)d_in[3];
    const float* e_nrm = (const float*)d_in[4];
    const int*   e_idx = (const int*)  d_in[5];
    const float* Wf  = (const float*)d_in[6];
    const float* bf  = (const float*)d_in[7];
    const float* Wm1 = (const float*)d_in[8];
    const float* bm1 = (const float*)d_in[9];
    const float* Wm2 = (const float*)d_in[10];
    const float* bm2 = (const float*)d_in[11];
    const float* WU  = (const float*)d_in[12];
    const float* WV  = (const float*)d_in[13];
    const float* Wa1 = (const float*)d_in[14];
    const float* ba1 = (const float*)d_in[15];
    const float* Wa2 = (const float*)d_in[16];
    const float* ba2 = (const float*)d_in[17];

    const int n  = in_sizes[0] / D;
    const int nE = in_sizes[2] / ES;

    float* out_s = (float*)d_out;
    float* out_v = out_s + (size_t)n * D;

    const size_t smem_c = (size_t)NT * (128 + 384 + 384 + 128 + 128 + 128 + 384) * sizeof(float);
    cudaFuncSetAttribute(node_update_kernel,
                         cudaFuncAttributeMaxDynamicSharedMemorySize, (int)smem_c);

    // CSR build
    zero_kernel<<<(n + 255) / 256, 256>>>(n);
    hist_kernel<<<(nE + 255) / 256, 256>>>(e_idx, nE);
    scan_kernel<<<1, 1024>>>(n);
    scatter_kernel<<<(nE + 255) / 256, 256>>>(e_st, e_vec, e_nrm, e_idx, nE);

    // scalar_output MLP (independent of CSR; same stream, runs after)
    node_mlp_kernel<<<(n + NT - 1) / NT, 128>>>(s_in, Wm1, bm1, Wm2, bm2, n);

    // node-centric message aggregation (writes s+ds, v+dv directly)
    aggregate_kernel<<<n, 128>>>(s_in, v_in, Wf, bf, out_s, out_v, n);

    // final node update
    node_update_kernel<<<(n + NT - 1) / NT, 128, smem_c>>>(WU, WV, Wa1, ba1, Wa2, ba2,
                                                           out_s, out_v, n);
}